// round 3
// baseline (speedup 1.0000x reference)
#include <cuda_runtime.h>

#define N_NODES   100000
#define N_EDGES   3200000
#define D_IN      128
#define D_H0      64
#define D_H1      32
#define N_GRAPHS  1024
#define N_CLASSES 16

#define SCAN_BS 1024
#define NB ((N_NODES + SCAN_BS - 1) / SCAN_BS)   // 98

// ---------------- scratch (static device globals; no runtime alloc) -----------
__device__ int   g_degcnt[N_NODES];
__device__ int   g_cursor[N_NODES];
__device__ int   g_rowptr[N_NODES];
__device__ float g_invsqrt[N_NODES];
__device__ int   g_col[N_EDGES];
__device__ float g_buf0[(size_t)N_NODES * D_H0];   // (X@W0)*invsqrt
__device__ float g_h0  [(size_t)N_NODES * D_H0];   // layer-0 output
__device__ float g_buf1[(size_t)N_NODES * D_H1];   // (h0@W1)*invsqrt
__device__ float g_pool[N_GRAPHS * D_H1];
__device__ int   g_pcnt[N_GRAPHS];
__device__ int   g_blocktot[NB];
__device__ int   g_blockoff[NB];

// ---------------- init ----------------
__global__ void k_init() {
    int i = blockIdx.x * blockDim.x + threadIdx.x;
    if (i < N_NODES) { g_degcnt[i] = 0; g_cursor[i] = 0; }
    if (i < N_GRAPHS * D_H1) g_pool[i] = 0.f;
    if (i < N_GRAPHS) g_pcnt[i] = 0;
}

// ---------------- degree count ----------------
__global__ void k_count(const int* __restrict__ ei) {
    int e = blockIdx.x * blockDim.x + threadIdx.x;
    if (e < N_EDGES) {
        int r = ei[e];                      // edge_index[0][e] = target
        atomicAdd(&g_degcnt[r], 1);
    }
}

// ---------------- prefix scan (3 kernels) ----------------
__global__ void k_scan1() {
    __shared__ int wsum[8];
    int t = threadIdx.x, b = blockIdx.x;
    int base = b * SCAN_BS + t * 4;
    int v[4];
#pragma unroll
    for (int k = 0; k < 4; k++) {
        int i = base + k;
        v[k] = (i < N_NODES) ? g_degcnt[i] : 0;
    }
    int tot = v[0] + v[1] + v[2] + v[3];
    int lane = t & 31, wid = t >> 5;
    int x = tot;
#pragma unroll
    for (int off = 1; off < 32; off <<= 1) {
        int y = __shfl_up_sync(0xffffffffu, x, off);
        if (lane >= off) x += y;
    }
    if (lane == 31) wsum[wid] = x;
    __syncthreads();
    if (t == 0) {
        int run = 0;
        for (int i = 0; i < 8; i++) { int tmp = wsum[i]; wsum[i] = run; run += tmp; }
        g_blocktot[b] = run;
    }
    __syncthreads();
    int run = wsum[wid] + (x - tot);   // exclusive prefix of this thread's first elem
#pragma unroll
    for (int k = 0; k < 4; k++) {
        int i = base + k;
        if (i < N_NODES) g_rowptr[i] = run;
        run += v[k];
    }
}

__global__ void k_scan2() {
    if (threadIdx.x == 0) {
        int run = 0;
        for (int i = 0; i < NB; i++) { g_blockoff[i] = run; run += g_blocktot[i]; }
    }
}

__global__ void k_scan3() {
    int i = blockIdx.x * blockDim.x + threadIdx.x;
    if (i < N_NODES) {
        g_rowptr[i] += g_blockoff[i / SCAN_BS];
        g_invsqrt[i] = rsqrtf((float)(g_degcnt[i] + 1));   // +1 self-loop
    }
}

// ---------------- scatter edges into CSR ----------------
__global__ void k_scatter(const int* __restrict__ ei) {
    int e = blockIdx.x * blockDim.x + threadIdx.x;
    if (e < N_EDGES) {
        int r = ei[e];
        int c = ei[N_EDGES + e];
        int pos = g_rowptr[r] + atomicAdd(&g_cursor[r], 1);
        g_col[pos] = c;
    }
}

// ---------------- GEMM0: g_buf0 = (x @ W0) * invsqrt ----------------
__global__ void k_gemm0(const float* __restrict__ x, const float* __restrict__ W0) {
    __shared__ float As[64][17];
    __shared__ float Bs[16][64];
    int t = threadIdx.x;
    int tx = t % 16, ty = t / 16;
    int row0 = blockIdx.x * 64;
    float acc[4][4] = {};
    for (int kt = 0; kt < D_IN; kt += 16) {
#pragma unroll
        for (int l = t; l < 64 * 16; l += 256) {
            int r = l >> 4, c = l & 15;
            int gr = row0 + r;
            As[r][c] = (gr < N_NODES) ? x[(size_t)gr * D_IN + kt + c] : 0.f;
        }
#pragma unroll
        for (int l = t; l < 16 * 64; l += 256) {
            int kk = l >> 6, c = l & 63;
            Bs[kk][c] = W0[(size_t)(kt + kk) * D_H0 + c];
        }
        __syncthreads();
#pragma unroll
        for (int kk = 0; kk < 16; kk++) {
            float a[4], b[4];
#pragma unroll
            for (int i = 0; i < 4; i++) a[i] = As[ty * 4 + i][kk];
#pragma unroll
            for (int j = 0; j < 4; j++) b[j] = Bs[kk][tx * 4 + j];
#pragma unroll
            for (int i = 0; i < 4; i++)
#pragma unroll
                for (int j = 0; j < 4; j++) acc[i][j] += a[i] * b[j];
        }
        __syncthreads();
    }
#pragma unroll
    for (int i = 0; i < 4; i++) {
        int gr = row0 + ty * 4 + i;
        if (gr < N_NODES) {
            float is = g_invsqrt[gr];
#pragma unroll
            for (int j = 0; j < 4; j++)
                g_buf0[(size_t)gr * D_H0 + tx * 4 + j] = acc[i][j] * is;
        }
    }
}

// ---------------- aggregation, 64-dim: h0 = relu(is*(sum g0[col] + g0[i]) + b0)
__global__ void k_agg64(const float* __restrict__ b0) {
    int w = (blockIdx.x * blockDim.x + threadIdx.x) >> 5;
    int lane = threadIdx.x & 31;
    if (w >= N_NODES) return;
    int start = g_rowptr[w], cnt = g_degcnt[w];
    const float2* G = (const float2*)g_buf0;
    float2 acc = make_float2(0.f, 0.f);
    for (int base = 0; base < cnt; base += 32) {
        int idx = base + lane;
        int cc = (idx < cnt) ? g_col[start + idx] : 0;
        int m = cnt - base; if (m > 32) m = 32;
#pragma unroll 4
        for (int j = 0; j < m; j++) {
            int c = __shfl_sync(0xffffffffu, cc, j);
            float2 v = G[(size_t)c * 32 + lane];
            acc.x += v.x; acc.y += v.y;
        }
    }
    float2 s = G[(size_t)w * 32 + lane];
    float is = g_invsqrt[w];
    float o0 = fmaxf(is * (acc.x + s.x) + b0[2 * lane],     0.f);
    float o1 = fmaxf(is * (acc.y + s.y) + b0[2 * lane + 1], 0.f);
    ((float2*)g_h0)[(size_t)w * 32 + lane] = make_float2(o0, o1);
}

// ---------------- GEMM1: g_buf1 = (h0 @ W1) * invsqrt ----------------
__global__ void k_gemm1(const float* __restrict__ W1) {
    __shared__ float As[128][17];
    __shared__ float Bs[16][32];
    int t = threadIdx.x;
    int tx = t % 8, ty = t / 8;
    int row0 = blockIdx.x * 128;
    float acc[4][4] = {};
    for (int kt = 0; kt < D_H0; kt += 16) {
#pragma unroll
        for (int l = t; l < 128 * 16; l += 256) {
            int r = l >> 4, c = l & 15;
            int gr = row0 + r;
            As[r][c] = (gr < N_NODES) ? g_h0[(size_t)gr * D_H0 + kt + c] : 0.f;
        }
#pragma unroll
        for (int l = t; l < 16 * 32; l += 256) {
            int kk = l >> 5, c = l & 31;
            Bs[kk][c] = W1[(size_t)(kt + kk) * D_H1 + c];
        }
        __syncthreads();
#pragma unroll
        for (int kk = 0; kk < 16; kk++) {
            float a[4], b[4];
#pragma unroll
            for (int i = 0; i < 4; i++) a[i] = As[ty * 4 + i][kk];
#pragma unroll
            for (int j = 0; j < 4; j++) b[j] = Bs[kk][tx * 4 + j];
#pragma unroll
            for (int i = 0; i < 4; i++)
#pragma unroll
                for (int j = 0; j < 4; j++) acc[i][j] += a[i] * b[j];
        }
        __syncthreads();
    }
#pragma unroll
    for (int i = 0; i < 4; i++) {
        int gr = row0 + ty * 4 + i;
        if (gr < N_NODES) {
            float is = g_invsqrt[gr];
#pragma unroll
            for (int j = 0; j < 4; j++)
                g_buf1[(size_t)gr * D_H1 + tx * 4 + j] = acc[i][j] * is;
        }
    }
}

// ---------------- aggregation, 32-dim + fused mean-pool accumulation ----------
__global__ void k_agg32(const float* __restrict__ b1,
                        const int* __restrict__ ngi) {
    int w = (blockIdx.x * blockDim.x + threadIdx.x) >> 5;
    int lane = threadIdx.x & 31;
    if (w >= N_NODES) return;
    int start = g_rowptr[w], cnt = g_degcnt[w];
    const float* G = g_buf1;
    float acc = 0.f;
    for (int base = 0; base < cnt; base += 32) {
        int idx = base + lane;
        int cc = (idx < cnt) ? g_col[start + idx] : 0;
        int m = cnt - base; if (m > 32) m = 32;
#pragma unroll 4
        for (int j = 0; j < m; j++) {
            int c = __shfl_sync(0xffffffffu, cc, j);
            acc += G[(size_t)c * D_H1 + lane];
        }
    }
    float s = G[(size_t)w * D_H1 + lane];
    float is = g_invsqrt[w];
    float o = fmaxf(is * (acc + s) + b1[lane], 0.f);
    int g = ngi[w];
    atomicAdd(&g_pool[g * D_H1 + lane], o);
    if (lane == 0) atomicAdd(&g_pcnt[g], 1);
}

// ---------------- head: out = (pool/cnt) @ Wd + bd ----------------
__global__ void k_final(const float* __restrict__ Wd, const float* __restrict__ bd,
                        float* __restrict__ out) {
    int w = (blockIdx.x * blockDim.x + threadIdx.x) >> 5;
    int lane = threadIdx.x & 31;
    if (w >= N_GRAPHS) return;
    float v = g_pool[w * D_H1 + lane];
    float invc = 1.f / fmaxf((float)g_pcnt[w], 1.f);
    float acc = 0.f;
#pragma unroll
    for (int j = 0; j < 32; j++) {
        float pj = __shfl_sync(0xffffffffu, v, j);
        if (lane < N_CLASSES) acc += pj * Wd[j * N_CLASSES + lane];
    }
    if (lane < N_CLASSES)
        out[w * N_CLASSES + lane] = acc * invc + bd[lane];
}

// ---------------- launch ----------------
extern "C" void kernel_launch(void* const* d_in, const int* in_sizes, int n_in,
                              void* d_out, int out_size) {
    const float* x   = (const float*)d_in[0];
    const int*   ei  = (const int*)d_in[1];
    const int*   ngi = (const int*)d_in[2];
    const float* W0  = (const float*)d_in[3];
    const float* b0  = (const float*)d_in[4];
    const float* W1  = (const float*)d_in[5];
    const float* b1  = (const float*)d_in[6];
    const float* Wd  = (const float*)d_in[7];
    const float* bd  = (const float*)d_in[8];
    float* out = (float*)d_out;

    k_init   <<<(N_NODES + 255) / 256, 256>>>();
    k_count  <<<(N_EDGES + 255) / 256, 256>>>(ei);
    k_scan1  <<<NB, 256>>>();
    k_scan2  <<<1, 32>>>();
    k_scan3  <<<(N_NODES + 255) / 256, 256>>>();
    k_scatter<<<(N_EDGES + 255) / 256, 256>>>(ei);
    k_gemm0  <<<(N_NODES + 63) / 64, 256>>>(x, W0);
    k_agg64  <<<(N_NODES * 32 + 255) / 256, 256>>>(b0);
    k_gemm1  <<<(N_NODES + 127) / 128, 256>>>(W1);
    k_agg32  <<<(N_NODES * 32 + 255) / 256, 256>>>(b1, ngi);
    k_final  <<<(N_GRAPHS * 32 + 255) / 256, 256>>>(Wd, bd, out);
}

// round 4
// speedup vs baseline: 1.0751x; 1.0751x over previous
#include <cuda_runtime.h>
#include <cuda_fp16.h>

#define N_NODES   100000
#define N_EDGES   3200000
#define D_IN      128
#define D_H0      64
#define D_H1      32
#define N_GRAPHS  1024
#define N_CLASSES 16

#define SCAN_BS 1024
#define NB ((N_NODES + SCAN_BS - 1) / SCAN_BS)   // 98

// ---------------- scratch (static device globals; no runtime alloc) -----------
__device__ int     g_degcnt[N_NODES];
__device__ int     g_cursor[N_NODES];
__device__ int     g_rowptr[N_NODES];
__device__ float   g_invsqrt[N_NODES];
__device__ int     g_col[N_EDGES];
__device__ __half2 g_buf0h[(size_t)N_NODES * 32];   // (X@W0)*invsqrt, fp16, 64 vals/row
__device__ __half  g_buf1h[(size_t)N_NODES * 32];   // (h0@W1)*invsqrt, fp16, 32 vals/row
__device__ float   g_pool[N_GRAPHS * D_H1];
__device__ int     g_pcnt[N_GRAPHS];
__device__ int     g_blocktot[NB];
__device__ int     g_blockoff[NB];

// ---------------- init ----------------
__global__ void k_init() {
    int i = blockIdx.x * blockDim.x + threadIdx.x;
    if (i < N_NODES) { g_degcnt[i] = 0; g_cursor[i] = 0; }
    if (i < N_GRAPHS * D_H1) g_pool[i] = 0.f;
    if (i < N_GRAPHS) g_pcnt[i] = 0;
}

// ---------------- degree count ----------------
__global__ void k_count(const int* __restrict__ ei) {
    int e = blockIdx.x * blockDim.x + threadIdx.x;
    if (e < N_EDGES) atomicAdd(&g_degcnt[ei[e]], 1);
}

// ---------------- prefix scan ----------------
__global__ void k_scan1() {
    __shared__ int wsum[8];
    int t = threadIdx.x, b = blockIdx.x;
    int base = b * SCAN_BS + t * 4;
    int v[4];
#pragma unroll
    for (int k = 0; k < 4; k++) {
        int i = base + k;
        v[k] = (i < N_NODES) ? g_degcnt[i] : 0;
    }
    int tot = v[0] + v[1] + v[2] + v[3];
    int lane = t & 31, wid = t >> 5;
    int x = tot;
#pragma unroll
    for (int off = 1; off < 32; off <<= 1) {
        int y = __shfl_up_sync(0xffffffffu, x, off);
        if (lane >= off) x += y;
    }
    if (lane == 31) wsum[wid] = x;
    __syncthreads();
    if (t == 0) {
        int run = 0;
        for (int i = 0; i < 8; i++) { int tmp = wsum[i]; wsum[i] = run; run += tmp; }
        g_blocktot[b] = run;
    }
    __syncthreads();
    int run = wsum[wid] + (x - tot);
#pragma unroll
    for (int k = 0; k < 4; k++) {
        int i = base + k;
        if (i < N_NODES) g_rowptr[i] = run;
        run += v[k];
    }
}

// single-warp shfl scan over NB block totals (was serial loop)
__global__ void k_scan2() {
    int lane = threadIdx.x;
    int carry = 0;
    for (int base = 0; base < NB; base += 32) {
        int i = base + lane;
        int v = (i < NB) ? g_blocktot[i] : 0;
        int x = v;
#pragma unroll
        for (int off = 1; off < 32; off <<= 1) {
            int y = __shfl_up_sync(0xffffffffu, x, off);
            if (lane >= off) x += y;
        }
        if (i < NB) g_blockoff[i] = x - v + carry;
        carry += __shfl_sync(0xffffffffu, x, 31);
    }
}

__global__ void k_scan3() {
    int i = blockIdx.x * blockDim.x + threadIdx.x;
    if (i < N_NODES) {
        g_rowptr[i] += g_blockoff[i / SCAN_BS];
        g_invsqrt[i] = rsqrtf((float)(g_degcnt[i] + 1));   // +1 self-loop
    }
}

// ---------------- scatter edges into CSR ----------------
__global__ void k_scatter(const int* __restrict__ ei) {
    int e = blockIdx.x * blockDim.x + threadIdx.x;
    if (e < N_EDGES) {
        int r = ei[e];
        int c = ei[N_EDGES + e];
        int pos = g_rowptr[r] + atomicAdd(&g_cursor[r], 1);
        g_col[pos] = c;
    }
}

// ---------------- GEMM0: g_buf0h = fp16((x @ W0) * invsqrt) ----------------
__global__ void k_gemm0(const float* __restrict__ x, const float* __restrict__ W0) {
    __shared__ float As[64][17];
    __shared__ float Bs[16][64];
    int t = threadIdx.x;
    int tx = t % 16, ty = t / 16;
    int row0 = blockIdx.x * 64;
    float acc[4][4] = {};
    for (int kt = 0; kt < D_IN; kt += 16) {
#pragma unroll
        for (int l = t; l < 64 * 16; l += 256) {
            int r = l >> 4, c = l & 15;
            int gr = row0 + r;
            As[r][c] = (gr < N_NODES) ? x[(size_t)gr * D_IN + kt + c] : 0.f;
        }
#pragma unroll
        for (int l = t; l < 16 * 64; l += 256) {
            int kk = l >> 6, c = l & 63;
            Bs[kk][c] = W0[(size_t)(kt + kk) * D_H0 + c];
        }
        __syncthreads();
#pragma unroll
        for (int kk = 0; kk < 16; kk++) {
            float a[4], b[4];
#pragma unroll
            for (int i = 0; i < 4; i++) a[i] = As[ty * 4 + i][kk];
#pragma unroll
            for (int j = 0; j < 4; j++) b[j] = Bs[kk][tx * 4 + j];
#pragma unroll
            for (int i = 0; i < 4; i++)
#pragma unroll
                for (int j = 0; j < 4; j++) acc[i][j] += a[i] * b[j];
        }
        __syncthreads();
    }
#pragma unroll
    for (int i = 0; i < 4; i++) {
        int gr = row0 + ty * 4 + i;
        if (gr < N_NODES) {
            float is = g_invsqrt[gr];
            g_buf0h[(size_t)gr * 32 + tx * 2]     = __floats2half2_rn(acc[i][0] * is, acc[i][1] * is);
            g_buf0h[(size_t)gr * 32 + tx * 2 + 1] = __floats2half2_rn(acc[i][2] * is, acc[i][3] * is);
        }
    }
}

// ---------------- agg64 + fused GEMM1:
//   h0 = relu(is*(sum buf0[col] + buf0[i]) + b0)   (held in registers, fp32)
//   buf1 = fp16((h0 @ W1) * is)
__global__ void k_agg64(const float* __restrict__ b0, const float* __restrict__ W1) {
    __shared__ float W1s[64][32];
    int t = threadIdx.x;
#pragma unroll
    for (int l = t; l < 64 * 32; l += 256) W1s[l >> 5][l & 31] = W1[l];
    __syncthreads();

    int w = (blockIdx.x * blockDim.x + t) >> 5;
    int lane = t & 31;
    if (w >= N_NODES) return;
    int start = g_rowptr[w], cnt = g_degcnt[w];
    const __half2* G = g_buf0h;
    float2 acc = make_float2(0.f, 0.f);
    for (int base = 0; base < cnt; base += 32) {
        int idx = base + lane;
        int cc = (idx < cnt) ? g_col[start + idx] : 0;
        int m = cnt - base; if (m > 32) m = 32;
#pragma unroll 8
        for (int j = 0; j < m; j++) {
            int c = __shfl_sync(0xffffffffu, cc, j);
            float2 v = __half22float2(G[(size_t)c * 32 + lane]);
            acc.x += v.x; acc.y += v.y;
        }
    }
    float2 s = __half22float2(G[(size_t)w * 32 + lane]);
    float is = g_invsqrt[w];
    float h0a = fmaxf(is * (acc.x + s.x) + b0[2 * lane],     0.f);
    float h0b = fmaxf(is * (acc.y + s.y) + b0[2 * lane + 1], 0.f);

    // fused h0 @ W1 (64x32) within the warp
    float d = 0.f;
#pragma unroll
    for (int kk = 0; kk < 32; kk++) {
        float a0 = __shfl_sync(0xffffffffu, h0a, kk);
        float a1 = __shfl_sync(0xffffffffu, h0b, kk);
        d += a0 * W1s[2 * kk][lane] + a1 * W1s[2 * kk + 1][lane];
    }
    g_buf1h[(size_t)w * 32 + lane] = __float2half(d * is);
}

// ---------------- agg32 + fused mean-pool accumulation ----------
__global__ void k_agg32(const float* __restrict__ b1,
                        const int* __restrict__ ngi) {
    int w = (blockIdx.x * blockDim.x + threadIdx.x) >> 5;
    int lane = threadIdx.x & 31;
    if (w >= N_NODES) return;
    int start = g_rowptr[w], cnt = g_degcnt[w];
    const __half* G = g_buf1h;
    float acc = 0.f;
    for (int base = 0; base < cnt; base += 32) {
        int idx = base + lane;
        int cc = (idx < cnt) ? g_col[start + idx] : 0;
        int m = cnt - base; if (m > 32) m = 32;
#pragma unroll 8
        for (int j = 0; j < m; j++) {
            int c = __shfl_sync(0xffffffffu, cc, j);
            acc += __half2float(G[(size_t)c * 32 + lane]);
        }
    }
    float s = __half2float(G[(size_t)w * 32 + lane]);
    float is = g_invsqrt[w];
    float o = fmaxf(is * (acc + s) + b1[lane], 0.f);
    int g = ngi[w];
    atomicAdd(&g_pool[g * D_H1 + lane], o);
    if (lane == 0) atomicAdd(&g_pcnt[g], 1);
}

// ---------------- head: out = (pool/cnt) @ Wd + bd ----------------
__global__ void k_final(const float* __restrict__ Wd, const float* __restrict__ bd,
                        float* __restrict__ out) {
    int w = (blockIdx.x * blockDim.x + threadIdx.x) >> 5;
    int lane = threadIdx.x & 31;
    if (w >= N_GRAPHS) return;
    float v = g_pool[w * D_H1 + lane];
    float invc = 1.f / fmaxf((float)g_pcnt[w], 1.f);
    float acc = 0.f;
#pragma unroll
    for (int j = 0; j < 32; j++) {
        float pj = __shfl_sync(0xffffffffu, v, j);
        if (lane < N_CLASSES) acc += pj * Wd[j * N_CLASSES + lane];
    }
    if (lane < N_CLASSES)
        out[w * N_CLASSES + lane] = acc * invc + bd[lane];
}

// ---------------- launch ----------------
extern "C" void kernel_launch(void* const* d_in, const int* in_sizes, int n_in,
                              void* d_out, int out_size) {
    const float* x   = (const float*)d_in[0];
    const int*   ei  = (const int*)d_in[1];
    const int*   ngi = (const int*)d_in[2];
    const float* W0  = (const float*)d_in[3];
    const float* b0  = (const float*)d_in[4];
    const float* W1  = (const float*)d_in[5];
    const float* b1  = (const float*)d_in[6];
    const float* Wd  = (const float*)d_in[7];
    const float* bd  = (const float*)d_in[8];
    float* out = (float*)d_out;

    k_init   <<<(N_NODES + 255) / 256, 256>>>();
    k_count  <<<(N_EDGES + 255) / 256, 256>>>(ei);
    k_scan1  <<<NB, 256>>>();
    k_scan2  <<<1, 32>>>();
    k_scan3  <<<(N_NODES + 255) / 256, 256>>>();
    k_scatter<<<(N_EDGES + 255) / 256, 256>>>(ei);
    k_gemm0  <<<(N_NODES + 63) / 64, 256>>>(x, W0);
    k_agg64  <<<(N_NODES * 32 + 255) / 256, 256>>>(b0, W1);
    k_agg32  <<<(N_NODES * 32 + 255) / 256, 256>>>(b1, ngi);
    k_final  <<<(N_GRAPHS * 32 + 255) / 256, 256>>>(Wd, bd, out);
}

// round 5
// speedup vs baseline: 1.1786x; 1.0963x over previous
#include <cuda_runtime.h>
#include <cuda_fp16.h>

#define N_NODES   100000
#define N_EDGES   3200000
#define D_IN      128
#define D_H0      64
#define D_H1      32
#define N_GRAPHS  1024
#define N_CLASSES 16

#define SCAN_BS 1024
#define NB ((N_NODES + SCAN_BS - 1) / SCAN_BS)   // 98

// ---------------- scratch ----------------
__device__ int     g_degcnt[N_NODES];
__device__ int     g_cursor[N_NODES];
__device__ int     g_rowptr[N_NODES];
__device__ float   g_invsqrt[N_NODES];
__device__ int     g_col[N_EDGES];
__device__ __half2 g_buf0h[(size_t)N_NODES * 32];   // (X@W0)*invsqrt, fp16
__device__ __half  g_buf1h[(size_t)N_NODES * 32];   // (h0@W1)*invsqrt, fp16
__device__ float   g_pool[N_GRAPHS * D_H1];
__device__ int     g_pcnt[N_GRAPHS];
__device__ int     g_blocktot[NB];
__device__ int     g_blockoff[NB];
__device__ int     g_scan_done;

// ---- f32x2 packed-FMA helpers (sm_103a dual-rate fp32, PTX-only) ----
__device__ __forceinline__ unsigned long long pk2(float x, float y) {
    unsigned long long r;
    asm("mov.b64 %0, {%1, %2};" : "=l"(r) : "f"(x), "f"(y));
    return r;
}
__device__ __forceinline__ void ffma2(unsigned long long& d,
                                      unsigned long long a, unsigned long long b) {
    asm("fma.rn.f32x2 %0, %1, %2, %0;" : "+l"(d) : "l"(a), "l"(b));
}

// ---------------- init ----------------
__global__ void k_init() {
    int i = blockIdx.x * blockDim.x + threadIdx.x;
    if (i < N_NODES) g_degcnt[i] = 0;
    if (i == 0) g_scan_done = 0;
}

// ---------------- degree count ----------------
__global__ void k_count(const int* __restrict__ ei) {
    int e = blockIdx.x * blockDim.x + threadIdx.x;
    if (e < N_EDGES) atomicAdd(&g_degcnt[ei[e]], 1);
}

// ---------------- invsqrt (needs only degrees) + pool init ----------------
__global__ void k_invsqrt() {
    int i = blockIdx.x * blockDim.x + threadIdx.x;
    if (i < N_NODES) g_invsqrt[i] = rsqrtf((float)(g_degcnt[i] + 1));
    if (i < N_GRAPHS * D_H1) g_pool[i] = 0.f;
    if (i < N_GRAPHS) g_pcnt[i] = 0;
}

// ---------------- scan1 + fused block-total scan (last-block lookback) -------
__global__ void k_scan12() {
    __shared__ int wsum[8];
    __shared__ int isLast;
    int t = threadIdx.x, b = blockIdx.x;
    int base = b * SCAN_BS + t * 4;
    int v[4];
#pragma unroll
    for (int k = 0; k < 4; k++) {
        int i = base + k;
        v[k] = (i < N_NODES) ? g_degcnt[i] : 0;
    }
    int tot = v[0] + v[1] + v[2] + v[3];
    int lane = t & 31, wid = t >> 5;
    int x = tot;
#pragma unroll
    for (int off = 1; off < 32; off <<= 1) {
        int y = __shfl_up_sync(0xffffffffu, x, off);
        if (lane >= off) x += y;
    }
    if (lane == 31) wsum[wid] = x;
    __syncthreads();
    if (t == 0) {
        int run = 0;
        for (int i = 0; i < 8; i++) { int tmp = wsum[i]; wsum[i] = run; run += tmp; }
        g_blocktot[b] = run;
    }
    __syncthreads();
    int run = wsum[wid] + (x - tot);
#pragma unroll
    for (int k = 0; k < 4; k++) {
        int i = base + k;
        if (i < N_NODES) g_rowptr[i] = run;
        run += v[k];
    }
    // last finishing block scans the 98 block totals (replaces k_scan2 launch)
    if (t == 0) {
        __threadfence();
        int d = atomicAdd(&g_scan_done, 1);
        isLast = (d == NB - 1);
    }
    __syncthreads();
    if (isLast && t < 32) {
        int carry = 0;
        for (int bb = 0; bb < NB; bb += 32) {
            int i = bb + t;
            int vv = (i < NB) ? g_blocktot[i] : 0;
            int xx = vv;
#pragma unroll
            for (int off = 1; off < 32; off <<= 1) {
                int y = __shfl_up_sync(0xffffffffu, xx, off);
                if (t >= off) xx += y;
            }
            if (i < NB) g_blockoff[i] = xx - vv + carry;
            carry += __shfl_sync(0xffffffffu, xx, 31);
        }
    }
}

__global__ void k_scan3() {
    int i = blockIdx.x * blockDim.x + threadIdx.x;
    if (i < N_NODES) {
        int rp = g_rowptr[i] + g_blockoff[i / SCAN_BS];
        g_rowptr[i] = rp;
        g_cursor[i] = rp;
    }
}

// ---------------- scatter edges into CSR ----------------
__global__ void k_scatter(const int* __restrict__ ei) {
    int e = blockIdx.x * blockDim.x + threadIdx.x;
    if (e < N_EDGES) {
        int r = ei[e];
        int c = ei[N_EDGES + e];
        int pos = atomicAdd(&g_cursor[r], 1);
        g_col[pos] = c;
    }
}

// ---------------- GEMM0 (f32x2 dual-rate): buf0h = fp16((x@W0)*invsqrt) -----
__global__ void k_gemm0(const float* __restrict__ x, const float* __restrict__ W0) {
    __shared__ float As[64][17];
    __shared__ float Bs[16][64];
    int t = threadIdx.x;
    int tx = t % 16, ty = t / 16;
    int row0 = blockIdx.x * 64;
    unsigned long long acc2[4][2];
#pragma unroll
    for (int i = 0; i < 4; i++) { acc2[i][0] = 0ull; acc2[i][1] = 0ull; }

    for (int kt = 0; kt < D_IN; kt += 16) {
        // load A tile via float4 (64x16 = 256 float4s)
        {
            int r = t >> 2, c4 = t & 3;
            int gr = row0 + r;
            float4 v = (gr < N_NODES)
                ? *(const float4*)&x[(size_t)gr * D_IN + kt + c4 * 4]
                : make_float4(0.f, 0.f, 0.f, 0.f);
            As[r][c4 * 4 + 0] = v.x; As[r][c4 * 4 + 1] = v.y;
            As[r][c4 * 4 + 2] = v.z; As[r][c4 * 4 + 3] = v.w;
        }
#pragma unroll
        for (int l = t; l < 16 * 64; l += 256) {
            int kk = l >> 6, c = l & 63;
            Bs[kk][c] = W0[(size_t)(kt + kk) * D_H0 + c];
        }
        __syncthreads();
#pragma unroll
        for (int kk = 0; kk < 16; kk++) {
            unsigned long long b0p = *(const unsigned long long*)&Bs[kk][tx * 4];
            unsigned long long b1p = *(const unsigned long long*)&Bs[kk][tx * 4 + 2];
#pragma unroll
            for (int i = 0; i < 4; i++) {
                float a = As[ty * 4 + i][kk];
                unsigned long long ap = pk2(a, a);
                ffma2(acc2[i][0], ap, b0p);
                ffma2(acc2[i][1], ap, b1p);
            }
        }
        __syncthreads();
    }
#pragma unroll
    for (int i = 0; i < 4; i++) {
        int gr = row0 + ty * 4 + i;
        if (gr < N_NODES) {
            float is = g_invsqrt[gr];
            float2 r0 = *(float2*)&acc2[i][0];
            float2 r1 = *(float2*)&acc2[i][1];
            g_buf0h[(size_t)gr * 32 + tx * 2]     = __floats2half2_rn(r0.x * is, r0.y * is);
            g_buf0h[(size_t)gr * 32 + tx * 2 + 1] = __floats2half2_rn(r1.x * is, r1.y * is);
        }
    }
}

// ---------------- agg64 + fused GEMM1 ----------------
__global__ void __launch_bounds__(512) k_agg64(const float* __restrict__ b0,
                                               const float* __restrict__ W1) {
    __shared__ float W1s[64][32];
    int t = threadIdx.x;
#pragma unroll
    for (int l = t; l < 64 * 32; l += 512) W1s[l >> 5][l & 31] = W1[l];
    __syncthreads();

    int w = (blockIdx.x * blockDim.x + t) >> 5;
    int lane = t & 31;
    if (w >= N_NODES) return;
    int start = g_rowptr[w], cnt = g_degcnt[w];
    const __half2* G = g_buf0h;
    float2 acc = make_float2(0.f, 0.f);
    for (int base = 0; base < cnt; base += 32) {
        int idx = base + lane;
        int cc = (idx < cnt) ? g_col[start + idx] : 0;
        int m = cnt - base; if (m > 32) m = 32;
#pragma unroll 8
        for (int j = 0; j < m; j++) {
            int c = __shfl_sync(0xffffffffu, cc, j);
            float2 v = __half22float2(G[(size_t)c * 32 + lane]);
            acc.x += v.x; acc.y += v.y;
        }
    }
    float2 s = __half22float2(G[(size_t)w * 32 + lane]);
    float is = g_invsqrt[w];
    float h0a = fmaxf(is * (acc.x + s.x) + b0[2 * lane],     0.f);
    float h0b = fmaxf(is * (acc.y + s.y) + b0[2 * lane + 1], 0.f);

    float d = 0.f;
#pragma unroll
    for (int kk = 0; kk < 32; kk++) {
        float a0 = __shfl_sync(0xffffffffu, h0a, kk);
        float a1 = __shfl_sync(0xffffffffu, h0b, kk);
        d += a0 * W1s[2 * kk][lane] + a1 * W1s[2 * kk + 1][lane];
    }
    g_buf1h[(size_t)w * 32 + lane] = __float2half(d * is);
}

// ---------------- agg32 + fused mean-pool ----------------
__global__ void __launch_bounds__(512) k_agg32(const float* __restrict__ b1,
                                               const int* __restrict__ ngi) {
    int w = (blockIdx.x * blockDim.x + threadIdx.x) >> 5;
    int lane = threadIdx.x & 31;
    if (w >= N_NODES) return;
    int start = g_rowptr[w], cnt = g_degcnt[w];
    const __half* G = g_buf1h;
    float acc = 0.f;
    for (int base = 0; base < cnt; base += 32) {
        int idx = base + lane;
        int cc = (idx < cnt) ? g_col[start + idx] : 0;
        int m = cnt - base; if (m > 32) m = 32;
#pragma unroll 8
        for (int j = 0; j < m; j++) {
            int c = __shfl_sync(0xffffffffu, cc, j);
            acc += __half2float(G[(size_t)c * 32 + lane]);
        }
    }
    float s = __half2float(G[(size_t)w * 32 + lane]);
    float is = g_invsqrt[w];
    float o = fmaxf(is * (acc + s) + b1[lane], 0.f);
    int g = ngi[w];
    atomicAdd(&g_pool[g * D_H1 + lane], o);
    if (lane == 0) atomicAdd(&g_pcnt[g], 1);
}

// ---------------- head ----------------
__global__ void k_final(const float* __restrict__ Wd, const float* __restrict__ bd,
                        float* __restrict__ out) {
    int w = (blockIdx.x * blockDim.x + threadIdx.x) >> 5;
    int lane = threadIdx.x & 31;
    if (w >= N_GRAPHS) return;
    float v = g_pool[w * D_H1 + lane];
    float invc = 1.f / fmaxf((float)g_pcnt[w], 1.f);
    float acc = 0.f;
#pragma unroll
    for (int j = 0; j < 32; j++) {
        float pj = __shfl_sync(0xffffffffu, v, j);
        if (lane < N_CLASSES) acc += pj * Wd[j * N_CLASSES + lane];
    }
    if (lane < N_CLASSES)
        out[w * N_CLASSES + lane] = acc * invc + bd[lane];
}

// ---------------- launch: fork CSR-build ∥ gemm0 ----------------
extern "C" void kernel_launch(void* const* d_in, const int* in_sizes, int n_in,
                              void* d_out, int out_size) {
    const float* x   = (const float*)d_in[0];
    const int*   ei  = (const int*)d_in[1];
    const int*   ngi = (const int*)d_in[2];
    const float* W0  = (const float*)d_in[3];
    const float* b0  = (const float*)d_in[4];
    const float* W1  = (const float*)d_in[5];
    const float* b1  = (const float*)d_in[6];
    const float* Wd  = (const float*)d_in[7];
    const float* bd  = (const float*)d_in[8];
    float* out = (float*)d_out;

    static cudaStream_t s1 = nullptr;
    static cudaEvent_t evFork = nullptr, evJoin = nullptr;
    if (!s1) {   // created once, before first graph capture (correctness call)
        cudaStreamCreateWithFlags(&s1, cudaStreamNonBlocking);
        cudaEventCreateWithFlags(&evFork, cudaEventDisableTiming);
        cudaEventCreateWithFlags(&evJoin, cudaEventDisableTiming);
    }

    k_init   <<<(N_NODES + 255) / 256, 256>>>();
    k_count  <<<(N_EDGES + 255) / 256, 256>>>(ei);
    k_invsqrt<<<(N_NODES + 255) / 256, 256>>>();

    cudaEventRecord(evFork, 0);
    cudaStreamWaitEvent(s1, evFork, 0);

    // side stream: CSR build
    k_scan12 <<<NB, 256, 0, s1>>>();
    k_scan3  <<<(N_NODES + 255) / 256, 256, 0, s1>>>();
    k_scatter<<<(N_EDGES + 255) / 256, 256, 0, s1>>>(ei);
    cudaEventRecord(evJoin, s1);

    // main stream: dense transform, overlapped with CSR build
    k_gemm0  <<<(N_NODES + 63) / 64, 256>>>(x, W0);

    cudaStreamWaitEvent(0, evJoin, 0);
    k_agg64  <<<(N_NODES * 32 + 511) / 512, 512>>>(b0, W1);
    k_agg32  <<<(N_NODES * 32 + 511) / 512, 512>>>(b1, ngi);
    k_final  <<<(N_GRAPHS * 32 + 255) / 256, 256>>>(Wd, bd, out);
}